// round 10
// baseline (speedup 1.0000x reference)
#include <cuda_runtime.h>
#include <cuda_bf16.h>
#include <math.h>
#include <stdint.h>

#define B_   2
#define T_   2048
#define D_   2048
#define H_   16
#define HD_  128
#define LAT_ 512
#define RD_  64
#define CD_  64
#define M_   (B_*T_)   // 4096 rows total

// ================= scratch =================
__device__ float g_Q [M_*D_];
__device__ float g_KV[M_*2*LAT_];
__device__ float g_KR[M_*RD_];
__device__ float g_KC[M_*H_*CD_];
__device__ float g_V [M_*D_];
__device__ float g_O [M_*D_];

__device__ __nv_bfloat16 g_xh [M_*D_],        g_xl [M_*D_];
__device__ __nv_bfloat16 g_Wqh [D_*D_],       g_Wql [D_*D_];
__device__ __nv_bfloat16 g_Wkvh[2*LAT_*D_],   g_Wkvl[2*LAT_*D_];
__device__ __nv_bfloat16 g_Wkrh[RD_*D_],      g_Wkrl[RD_*D_];
__device__ __nv_bfloat16 g_Wkuh[H_*CD_*LAT_], g_Wkul[H_*CD_*LAT_];
__device__ __nv_bfloat16 g_Wvuh[D_*LAT_],     g_Wvul[D_*LAT_];
__device__ __nv_bfloat16 g_Woh [D_*D_],       g_Wol [D_*D_];
__device__ __nv_bfloat16 g_KVh [M_*2*LAT_],   g_KVl [M_*2*LAT_];
__device__ __nv_bfloat16 g_Oh  [M_*D_],       g_Ol  [M_*D_];

// ================= fp32 -> (hi, lo) bf16 split =================
__global__ __launch_bounds__(256) void split_f32_bf16(
    const float* __restrict__ src,
    __nv_bfloat16* __restrict__ hi, __nv_bfloat16* __restrict__ lo, int n)
{
    int i = (blockIdx.x * 256 + threadIdx.x) * 4;
    if (i >= n) return;
    float4 v = *(const float4*)(src + i);
    __nv_bfloat16 h0 = __float2bfloat16(v.x), h1 = __float2bfloat16(v.y);
    __nv_bfloat16 h2 = __float2bfloat16(v.z), h3 = __float2bfloat16(v.w);
    __nv_bfloat16 l0 = __float2bfloat16(v.x - __bfloat162float(h0));
    __nv_bfloat16 l1 = __float2bfloat16(v.y - __bfloat162float(h1));
    __nv_bfloat16 l2 = __float2bfloat16(v.z - __bfloat162float(h2));
    __nv_bfloat16 l3 = __float2bfloat16(v.w - __bfloat162float(h3));
    __nv_bfloat162* hp = (__nv_bfloat162*)(hi + i);
    __nv_bfloat162* lp = (__nv_bfloat162*)(lo + i);
    hp[0] = __nv_bfloat162(h0, h1); hp[1] = __nv_bfloat162(h2, h3);
    lp[0] = __nv_bfloat162(l0, l1); lp[1] = __nv_bfloat162(l2, l3);
}

// ================= HMMA helpers (base ISA, legal on sm_103) =================
__device__ __forceinline__ void mma16816(float* c, const uint32_t* a, const uint32_t* b)
{
    asm volatile(
        "mma.sync.aligned.m16n8k16.row.col.f32.bf16.bf16.f32 "
        "{%0,%1,%2,%3}, {%4,%5,%6,%7}, {%8,%9}, {%0,%1,%2,%3};"
        : "+f"(c[0]), "+f"(c[1]), "+f"(c[2]), "+f"(c[3])
        : "r"(a[0]), "r"(a[1]), "r"(a[2]), "r"(a[3]), "r"(b[0]), "r"(b[1]));
}
__device__ __forceinline__ void ldsm_x4_trans(uint32_t* r, uint32_t addr)
{
    asm volatile(
        "ldmatrix.sync.aligned.m8n8.x4.trans.shared.b16 {%0,%1,%2,%3}, [%4];"
        : "=r"(r[0]), "=r"(r[1]), "=r"(r[2]), "=r"(r[3]) : "r"(addr));
}
__device__ __forceinline__ uint32_t smem_u32(const void* p)
{
    uint32_t a;
    asm("{ .reg .u64 t; cvta.to.shared.u64 t, %1; cvt.u32.u64 %0, t; }"
        : "=r"(a) : "l"(p));
    return a;
}

// ================= HMMA 3-pass split-bf16 GEMM (unchanged from R8) =================
template<int BN>
__global__ __launch_bounds__(256) void gemm_hmma_3p(
    const __nv_bfloat16* __restrict__ Ah, const __nv_bfloat16* __restrict__ Al,
    int lda, int aoff,
    const __nv_bfloat16* __restrict__ Bh, const __nv_bfloat16* __restrict__ Bl,
    const float* __restrict__ bias,
    float* __restrict__ C, int ldc, int Kdim)
{
    constexpr int KP = 40;
    constexpr int GC = BN / 32;
    constexpr int GR = 8 / GC;
    constexpr int WM = 128 / GR;
    constexpr int MA = WM / 16;

    __shared__ __nv_bfloat16 sA[2][128][KP];
    __shared__ __nv_bfloat16 sB[2][BN][KP];

    const int tid  = threadIdx.x;
    const int wid  = tid >> 5, lane = tid & 31;
    const int g    = lane >> 2, t = lane & 3;
    const int bm   = blockIdx.y * 128;
    const int bn   = blockIdx.x * BN;
    const int wm   = (wid / GC) * WM;
    const int wn   = (wid % GC) * 32;

    float acc[MA][4][4];
    #pragma unroll
    for (int im = 0; im < MA; im++)
        #pragma unroll
        for (int in_ = 0; in_ < 4; in_++)
            #pragma unroll
            for (int r = 0; r < 4; r++) acc[im][in_][r] = 0.f;

    for (int k0 = 0; k0 < Kdim; k0 += 32) {
        __syncthreads();
        #pragma unroll
        for (int it = 0; it < 2; it++) {
            int idx = (tid + it * 256) * 8;
            int row = idx >> 5, col = idx & 31;
            long go = (long)(bm + row) * lda + aoff + k0 + col;
            *(uint4*)&sA[0][row][col] = *(const uint4*)(Ah + go);
            *(uint4*)&sA[1][row][col] = *(const uint4*)(Al + go);
        }
        #pragma unroll
        for (int it = 0; it < BN / 64; it++) {
            int idx = (tid + it * 256) * 8;
            int row = idx >> 5, col = idx & 31;
            long go = (long)(bn + row) * Kdim + k0 + col;
            *(uint4*)&sB[0][row][col] = *(const uint4*)(Bh + go);
            *(uint4*)&sB[1][row][col] = *(const uint4*)(Bl + go);
        }
        __syncthreads();

        #pragma unroll
        for (int ks = 0; ks < 2; ks++) {
            const int kb = ks * 16;
            uint32_t ah[MA][4], al[MA][4];
            #pragma unroll
            for (int im = 0; im < MA; im++) {
                int r0 = wm + im * 16 + g;
                ah[im][0] = *(const uint32_t*)&sA[0][r0    ][kb + t*2];
                ah[im][1] = *(const uint32_t*)&sA[0][r0 + 8][kb + t*2];
                ah[im][2] = *(const uint32_t*)&sA[0][r0    ][kb + 8 + t*2];
                ah[im][3] = *(const uint32_t*)&sA[0][r0 + 8][kb + 8 + t*2];
                al[im][0] = *(const uint32_t*)&sA[1][r0    ][kb + t*2];
                al[im][1] = *(const uint32_t*)&sA[1][r0 + 8][kb + t*2];
                al[im][2] = *(const uint32_t*)&sA[1][r0    ][kb + 8 + t*2];
                al[im][3] = *(const uint32_t*)&sA[1][r0 + 8][kb + 8 + t*2];
            }
            uint32_t bh[4][2], bl[4][2];
            #pragma unroll
            for (int in_ = 0; in_ < 4; in_++) {
                int r = wn + in_ * 8 + g;
                bh[in_][0] = *(const uint32_t*)&sB[0][r][kb + t*2];
                bh[in_][1] = *(const uint32_t*)&sB[0][r][kb + 8 + t*2];
                bl[in_][0] = *(const uint32_t*)&sB[1][r][kb + t*2];
                bl[in_][1] = *(const uint32_t*)&sB[1][r][kb + 8 + t*2];
            }
            #pragma unroll
            for (int im = 0; im < MA; im++)
                #pragma unroll
                for (int in_ = 0; in_ < 4; in_++) {
                    mma16816(acc[im][in_], ah[im], bh[in_]);
                    mma16816(acc[im][in_], ah[im], bl[in_]);
                    mma16816(acc[im][in_], al[im], bh[in_]);
                }
        }
    }

    #pragma unroll
    for (int im = 0; im < MA; im++) {
        #pragma unroll
        for (int in_ = 0; in_ < 4; in_++) {
            int col = bn + wn + in_ * 8 + t * 2;
            float2 bv = *(const float2*)(bias + col);
            int r0 = bm + wm + im * 16 + g;
            float2 v0 = { acc[im][in_][0] + bv.x, acc[im][in_][1] + bv.y };
            float2 v1 = { acc[im][in_][2] + bv.x, acc[im][in_][3] + bv.y };
            *(float2*)(C + (long)r0 * ldc + col)       = v0;
            *(float2*)(C + (long)(r0 + 8) * ldc + col) = v1;
        }
    }
}

// ================= RoPE =================
__device__ __forceinline__ void rope_pair(int pos, int j, float& x1, float& x2)
{
    const float LOG2_THETA = 13.287712379549449f;
    float e   = (float)(2 * j) * (1.0f / (float)RD_);
    float inv = exp2f(-e * LOG2_THETA);
    float ang = (float)pos * inv;
    float s, c;
    sincosf(ang, &s, &c);
    float a = x1, b = x2;
    x1 = a * c - b * s;
    x2 = b * c + a * s;
}

__global__ void rope_kr_kernel()
{
    int r = blockIdx.x, j = threadIdx.x;
    int pos = r & (T_ - 1);
    float* p = g_KR + (long)r * RD_;
    float x1 = p[j], x2 = p[j + 32];
    rope_pair(pos, j, x1, x2);
    p[j] = x1; p[j + 32] = x2;
}

__global__ void rope_q_kernel()
{
    int r = blockIdx.x, tid = threadIdx.x;
    int h = tid >> 5, j = tid & 31;
    int pos = r & (T_ - 1);
    float* p = g_Q + (long)r * D_ + h * HD_ + CD_;
    float x1 = p[j], x2 = p[j + 32];
    rope_pair(pos, j, x1, x2);
    p[j] = x1; p[j + 32] = x2;
}

// ================= HMMA flash attention (3-pass split QK and PV) =================
#define KP2 136   // bf16 row stride for Q/K/V tiles (128 cols data)
#define PP  72    // bf16 row stride for P tiles (64 cols data)
#define FL2_SMEM (6*64*KP2*2 + 64*65*4 + 2*64*PP*2 + 3*64*4)   // 140288 B

__global__ __launch_bounds__(256) void flash_hmma()
{
    extern __shared__ char smx[];
    __nv_bfloat16* sQh = (__nv_bfloat16*)smx;
    __nv_bfloat16* sQl = sQh + 64*KP2;
    __nv_bfloat16* sKh = sQl + 64*KP2;
    __nv_bfloat16* sKl = sKh + 64*KP2;
    __nv_bfloat16* sVh = sKl + 64*KP2;
    __nv_bfloat16* sVl = sVh + 64*KP2;
    float*         sP  = (float*)(sVl + 64*KP2);     // [64][65]
    __nv_bfloat16* sPh = (__nv_bfloat16*)(sP + 64*65);
    __nv_bfloat16* sPl = sPh + 64*PP;
    float*         sM  = (float*)(sPl + 64*PP);
    float*         sL  = sM + 64;
    float*         sSc = sL + 64;

    const int qt = 31 - blockIdx.x;
    const int pr = blockIdx.y;
    const int b  = pr >> 4, h = pr & 15;
    const int tid  = threadIdx.x;
    const int wid  = tid >> 5, lane = tid & 31;
    const int g    = lane >> 2, t = lane & 3;
    const int q0 = qt * 64;
    const int rowbase = b * T_;
    const int wm  = (wid >> 1) * 16;       // query rows (both phases)
    const int wnS = (wid & 1) * 32;        // key cols (QK phase)
    const int wnO = (wid & 1) * 64;        // dim cols (PV phase)

    const uint32_t vhb = smem_u32(sVh);
    const uint32_t vlb = smem_u32(sVl);

    // ---- load Q tile, split hi/lo ----
    for (int idx = tid; idx < 64*128; idx += 256) {
        int qi = idx >> 7, d = idx & 127;
        float v = g_Q[(long)(rowbase + q0 + qi) * D_ + h*HD_ + d];
        __nv_bfloat16 hi = __float2bfloat16(v);
        sQh[qi*KP2 + d] = hi;
        sQl[qi*KP2 + d] = __float2bfloat16(v - __bfloat162float(hi));
    }
    if (tid < 64) { sM[tid] = -INFINITY; sL[tid] = 0.f; }

    float accO[8][4];
    #pragma unroll
    for (int a = 0; a < 8; a++)
        #pragma unroll
        for (int r = 0; r < 4; r++) accO[a][r] = 0.f;

    const float sc_qk = 0.08838834764831845f;

    for (int kb = 0; kb <= qt; kb++) {
        const int k0 = kb * 64;
        __syncthreads();   // S1: protect K/V tiles + sPh from previous iteration
        for (int idx = tid; idx < 64*128; idx += 256) {
            int ki = idx >> 7, d = idx & 127;
            long r = rowbase + k0 + ki;
            float kv = (d < CD_) ? g_KC[r * (H_*CD_) + h*CD_ + d]
                                 : g_KR[r * RD_ + (d - CD_)];
            __nv_bfloat16 kh = __float2bfloat16(kv);
            sKh[ki*KP2 + d] = kh;
            sKl[ki*KP2 + d] = __float2bfloat16(kv - __bfloat162float(kh));
            float vv = g_V[r * D_ + h*HD_ + d];
            __nv_bfloat16 vh = __float2bfloat16(vv);
            sVh[ki*KP2 + d] = vh;
            sVl[ki*KP2 + d] = __float2bfloat16(vv - __bfloat162float(vh));
        }
        __syncthreads();   // S2

        // ---- QK^T: S[wm:wm+16][wnS:wnS+32], 3-pass over 128 dims ----
        float accS[4][4];
        #pragma unroll
        for (int in_ = 0; in_ < 4; in_++)
            #pragma unroll
            for (int r = 0; r < 4; r++) accS[in_][r] = 0.f;

        #pragma unroll
        for (int ks = 0; ks < 8; ks++) {
            const int kk = ks * 16;
            uint32_t ah[4], al[4];
            ah[0] = *(const uint32_t*)&sQh[(wm+g  )*KP2 + kk     + t*2];
            ah[1] = *(const uint32_t*)&sQh[(wm+g+8)*KP2 + kk     + t*2];
            ah[2] = *(const uint32_t*)&sQh[(wm+g  )*KP2 + kk + 8 + t*2];
            ah[3] = *(const uint32_t*)&sQh[(wm+g+8)*KP2 + kk + 8 + t*2];
            al[0] = *(const uint32_t*)&sQl[(wm+g  )*KP2 + kk     + t*2];
            al[1] = *(const uint32_t*)&sQl[(wm+g+8)*KP2 + kk     + t*2];
            al[2] = *(const uint32_t*)&sQl[(wm+g  )*KP2 + kk + 8 + t*2];
            al[3] = *(const uint32_t*)&sQl[(wm+g+8)*KP2 + kk + 8 + t*2];
            #pragma unroll
            for (int in_ = 0; in_ < 4; in_++) {
                int r = wnS + in_*8 + g;
                uint32_t bh[2], bl[2];
                bh[0] = *(const uint32_t*)&sKh[r*KP2 + kk     + t*2];
                bh[1] = *(const uint32_t*)&sKh[r*KP2 + kk + 8 + t*2];
                bl[0] = *(const uint32_t*)&sKl[r*KP2 + kk     + t*2];
                bl[1] = *(const uint32_t*)&sKl[r*KP2 + kk + 8 + t*2];
                mma16816(accS[in_], ah, bh);
                mma16816(accS[in_], ah, bl);
                mma16816(accS[in_], al, bh);
            }
        }

        // ---- write masked, scaled S to sP ----
        {
            const bool diag = (kb == qt);
            #pragma unroll
            for (int in_ = 0; in_ < 4; in_++) {
                int c0 = wnS + in_*8 + t*2;
                int r0 = wm + g, r1 = wm + g + 8;
                float v0 = accS[in_][0] * sc_qk;
                float v1 = accS[in_][1] * sc_qk;
                float v2 = accS[in_][2] * sc_qk;
                float v3 = accS[in_][3] * sc_qk;
                if (diag) {
                    if (c0     > r0) v0 = -INFINITY;
                    if (c0 + 1 > r0) v1 = -INFINITY;
                    if (c0     > r1) v2 = -INFINITY;
                    if (c0 + 1 > r1) v3 = -INFINITY;
                }
                sP[r0*65 + c0] = v0; sP[r0*65 + c0 + 1] = v1;
                sP[r1*65 + c0] = v2; sP[r1*65 + c0 + 1] = v3;
            }
        }
        __syncthreads();   // S3

        // ---- online softmax stats (one thread per row) ----
        if (tid < 64) {
            float* row = sP + tid*65;
            float mold = sM[tid];
            float mx = mold;
            #pragma unroll 8
            for (int j = 0; j < 64; j++) mx = fmaxf(mx, row[j]);
            float scl = __expf(mold - mx);
            float sum = 0.f;
            #pragma unroll 8
            for (int j = 0; j < 64; j++) {
                float e = __expf(row[j] - mx);
                row[j] = e;
                sum += e;
            }
            sL[tid]  = sL[tid] * scl + sum;
            sM[tid]  = mx;
            sSc[tid] = scl;
        }
        __syncthreads();   // S4

        // ---- convert P to bf16 hi/lo (all 256 threads) ----
        for (int idx = tid; idx < 64*64; idx += 256) {
            int q = idx >> 6, j = idx & 63;
            float e = sP[q*65 + j];
            __nv_bfloat16 ph = __float2bfloat16(e);
            sPh[q*PP + j] = ph;
            sPl[q*PP + j] = __float2bfloat16(e - __bfloat162float(ph));
        }
        __syncthreads();   // S5

        // ---- rescale accO, then O += P V (3-pass) ----
        {
            float f0 = sSc[wm + g], f1 = sSc[wm + g + 8];
            #pragma unroll
            for (int a = 0; a < 8; a++) {
                accO[a][0] *= f0; accO[a][1] *= f0;
                accO[a][2] *= f1; accO[a][3] *= f1;
            }
        }
        #pragma unroll
        for (int ks = 0; ks < 4; ks++) {
            const int kk = ks * 16;
            uint32_t ah[4], al[4];
            ah[0] = *(const uint32_t*)&sPh[(wm+g  )*PP + kk     + t*2];
            ah[1] = *(const uint32_t*)&sPh[(wm+g+8)*PP + kk     + t*2];
            ah[2] = *(const uint32_t*)&sPh[(wm+g  )*PP + kk + 8 + t*2];
            ah[3] = *(const uint32_t*)&sPh[(wm+g+8)*PP + kk + 8 + t*2];
            al[0] = *(const uint32_t*)&sPl[(wm+g  )*PP + kk     + t*2];
            al[1] = *(const uint32_t*)&sPl[(wm+g+8)*PP + kk     + t*2];
            al[2] = *(const uint32_t*)&sPl[(wm+g  )*PP + kk + 8 + t*2];
            al[3] = *(const uint32_t*)&sPl[(wm+g+8)*PP + kk + 8 + t*2];
            #pragma unroll
            for (int pair = 0; pair < 4; pair++) {
                int n0 = wnO + pair * 16;
                int klocal = kk + (lane & 15);
                int dloc   = n0 + ((lane >> 4) << 3);
                uint32_t off = (uint32_t)(klocal * KP2 + dloc) * 2;
                uint32_t bh4[4], bl4[4];
                ldsm_x4_trans(bh4, vhb + off);
                ldsm_x4_trans(bl4, vlb + off);
                mma16816(accO[pair*2    ], ah, bh4);
                mma16816(accO[pair*2    ], ah, bl4);
                mma16816(accO[pair*2    ], al, bh4);
                mma16816(accO[pair*2 + 1], ah, bh4 + 2);
                mma16816(accO[pair*2 + 1], ah, bl4 + 2);
                mma16816(accO[pair*2 + 1], al, bh4 + 2);
            }
        }
    }

    // ---- final: divide by L, store O ----
    {
        float inv0 = 1.f / sL[wm + g];
        float inv1 = 1.f / sL[wm + g + 8];
        long r0 = (long)(rowbase + q0 + wm + g) * D_;
        long r1 = (long)(rowbase + q0 + wm + g + 8) * D_;
        #pragma unroll
        for (int a = 0; a < 8; a++) {
            int col = h*HD_ + wnO + (a >> 1) * 16 + (a & 1) * 8 + t*2;
            float2 v0 = { accO[a][0] * inv0, accO[a][1] * inv0 };
            float2 v1 = { accO[a][2] * inv1, accO[a][3] * inv1 };
            *(float2*)(g_O + r0 + col) = v0;
            *(float2*)(g_O + r1 + col) = v1;
        }
    }
}

// ================= launcher =================
extern "C" void kernel_launch(void* const* d_in, const int* in_sizes, int n_in,
                              void* d_out, int out_size)
{
    const float* x   = (const float*)d_in[0];
    const float* Wq  = (const float*)d_in[1];
    const float* bq  = (const float*)d_in[2];
    const float* Wkv = (const float*)d_in[3];
    const float* bkv = (const float*)d_in[4];
    const float* Wkr = (const float*)d_in[5];
    const float* bkr = (const float*)d_in[6];
    const float* Wku = (const float*)d_in[7];
    const float* bku = (const float*)d_in[8];
    const float* Wvu = (const float*)d_in[9];
    const float* bvu = (const float*)d_in[10];
    const float* Wo  = (const float*)d_in[11];
    const float* bo  = (const float*)d_in[12];
    float* out = (float*)d_out;

    void *pQ, *pKV, *pKR, *pKC, *pV, *pO;
    cudaGetSymbolAddress(&pQ,  g_Q);
    cudaGetSymbolAddress(&pKV, g_KV);
    cudaGetSymbolAddress(&pKR, g_KR);
    cudaGetSymbolAddress(&pKC, g_KC);
    cudaGetSymbolAddress(&pV,  g_V);
    cudaGetSymbolAddress(&pO,  g_O);
    void *pxh, *pxl, *pWqh, *pWql, *pWkvh, *pWkvl, *pWkrh, *pWkrl;
    void *pWkuh, *pWkul, *pWvuh, *pWvul, *pWoh, *pWol, *pKVh, *pKVl, *pOh, *pOl;
    cudaGetSymbolAddress(&pxh,  g_xh);   cudaGetSymbolAddress(&pxl,  g_xl);
    cudaGetSymbolAddress(&pWqh, g_Wqh);  cudaGetSymbolAddress(&pWql, g_Wql);
    cudaGetSymbolAddress(&pWkvh,g_Wkvh); cudaGetSymbolAddress(&pWkvl,g_Wkvl);
    cudaGetSymbolAddress(&pWkrh,g_Wkrh); cudaGetSymbolAddress(&pWkrl,g_Wkrl);
    cudaGetSymbolAddress(&pWkuh,g_Wkuh); cudaGetSymbolAddress(&pWkul,g_Wkul);
    cudaGetSymbolAddress(&pWvuh,g_Wvuh); cudaGetSymbolAddress(&pWvul,g_Wvul);
    cudaGetSymbolAddress(&pWoh, g_Woh);  cudaGetSymbolAddress(&pWol, g_Wol);
    cudaGetSymbolAddress(&pKVh, g_KVh);  cudaGetSymbolAddress(&pKVl, g_KVl);
    cudaGetSymbolAddress(&pOh,  g_Oh);   cudaGetSymbolAddress(&pOl,  g_Ol);

    cudaFuncSetAttribute(flash_hmma,
                         cudaFuncAttributeMaxDynamicSharedMemorySize, FL2_SMEM);

    auto SPL = [](const float* s, void* h, void* l, int n) {
        split_f32_bf16<<<n/1024, 256>>>(s, (__nv_bfloat16*)h, (__nv_bfloat16*)l, n);
    };

    // input + weight splits
    SPL(x,   pxh,   pxl,   M_*D_);
    SPL(Wq,  pWqh,  pWql,  D_*D_);
    SPL(Wkv, pWkvh, pWkvl, 2*LAT_*D_);
    SPL(Wkr, pWkrh, pWkrl, RD_*D_);
    SPL(Wku, pWkuh, pWkul, H_*CD_*LAT_);
    SPL(Wvu, pWvuh, pWvul, D_*LAT_);
    SPL(Wo,  pWoh,  pWol,  D_*D_);

    // Q = x Wq^T + bq
    gemm_hmma_3p<128><<<dim3(16, 32), 256>>>(
        (__nv_bfloat16*)pxh, (__nv_bfloat16*)pxl, D_, 0,
        (__nv_bfloat16*)pWqh, (__nv_bfloat16*)pWql, bq, (float*)pQ, D_, D_);
    // KV = x Wkv^T + bkv
    gemm_hmma_3p<128><<<dim3(8, 32), 256>>>(
        (__nv_bfloat16*)pxh, (__nv_bfloat16*)pxl, D_, 0,
        (__nv_bfloat16*)pWkvh, (__nv_bfloat16*)pWkvl, bkv, (float*)pKV, 2*LAT_, D_);
    // KR = x Wkr^T + bkr
    gemm_hmma_3p<64><<<dim3(1, 32), 256>>>(
        (__nv_bfloat16*)pxh, (__nv_bfloat16*)pxl, D_, 0,
        (__nv_bfloat16*)pWkrh, (__nv_bfloat16*)pWkrl, bkr, (float*)pKR, RD_, D_);
    rope_kr_kernel<<<M_, 32>>>();

    // split KV for up-projections
    SPL((const float*)pKV, pKVh, pKVl, M_*2*LAT_);

    // KC = k_lat Wku^T + bku
    gemm_hmma_3p<128><<<dim3(8, 32), 256>>>(
        (__nv_bfloat16*)pKVh, (__nv_bfloat16*)pKVl, 2*LAT_, 0,
        (__nv_bfloat16*)pWkuh, (__nv_bfloat16*)pWkul, bku, (float*)pKC, H_*CD_, LAT_);
    // V = v_lat Wvu^T + bvu
    gemm_hmma_3p<128><<<dim3(16, 32), 256>>>(
        (__nv_bfloat16*)pKVh, (__nv_bfloat16*)pKVl, 2*LAT_, LAT_,
        (__nv_bfloat16*)pWvuh, (__nv_bfloat16*)pWvul, bvu, (float*)pV, D_, LAT_);

    rope_q_kernel<<<M_, 512>>>();
    flash_hmma<<<dim3(32, 32), 256, FL2_SMEM>>>();

    // split O, then out = O Wo^T + bo
    SPL((const float*)pO, pOh, pOl, M_*D_);
    gemm_hmma_3p<128><<<dim3(16, 32), 256>>>(
        (__nv_bfloat16*)pOh, (__nv_bfloat16*)pOl, D_, 0,
        (__nv_bfloat16*)pWoh, (__nv_bfloat16*)pWol, bo, out, D_, D_);
}

// round 12
// speedup vs baseline: 1.2149x; 1.2149x over previous
#include <cuda_runtime.h>
#include <cuda_bf16.h>
#include <math.h>
#include <stdint.h>

#define B_   2
#define T_   2048
#define D_   2048
#define H_   16
#define HD_  128
#define LAT_ 512
#define RD_  64
#define CD_  64
#define M_   (B_*T_)   // 4096 rows total

typedef unsigned long long ull;

// ================= packed f32x2 helpers (flash kernel) =================
__device__ __forceinline__ ull ffma2(ull a, ull b, ull c) {
    ull d;
    asm("fma.rn.f32x2 %0, %1, %2, %3;" : "=l"(d) : "l"(a), "l"(b), "l"(c));
    return d;
}
__device__ __forceinline__ ull fmul2(ull a, ull b) {
    ull d;
    asm("mul.rn.f32x2 %0, %1, %2;" : "=l"(d) : "l"(a), "l"(b));
    return d;
}
__device__ __forceinline__ ull splat2(float x) {
    ull r;
    asm("mov.b64 %0, {%1, %1};" : "=l"(r) : "f"(x));
    return r;
}
__device__ __forceinline__ float2 unpack2(ull v) {
    float2 f;
    asm("mov.b64 {%0, %1}, %2;" : "=f"(f.x), "=f"(f.y) : "l"(v));
    return f;
}

// ================= scratch =================
__device__ float g_Q [M_*D_];
__device__ float g_KV[M_*2*LAT_];
__device__ float g_KR[M_*RD_];
__device__ float g_KC[M_*H_*CD_];
__device__ float g_V [M_*D_];
__device__ float g_O [M_*D_];

__device__ __nv_bfloat16 g_xh [M_*D_],        g_xl [M_*D_];
__device__ __nv_bfloat16 g_Wqh [D_*D_],       g_Wql [D_*D_];
__device__ __nv_bfloat16 g_Wkvh[2*LAT_*D_],   g_Wkvl[2*LAT_*D_];
__device__ __nv_bfloat16 g_Wkrh[RD_*D_],      g_Wkrl[RD_*D_];
__device__ __nv_bfloat16 g_Wkuh[H_*CD_*LAT_], g_Wkul[H_*CD_*LAT_];
__device__ __nv_bfloat16 g_Wvuh[D_*LAT_],     g_Wvul[D_*LAT_];
__device__ __nv_bfloat16 g_Woh [D_*D_],       g_Wol [D_*D_];
__device__ __nv_bfloat16 g_KVh [M_*2*LAT_],   g_KVl [M_*2*LAT_];
__device__ __nv_bfloat16 g_Oh  [M_*D_],       g_Ol  [M_*D_];

// ================= fp32 -> (hi, lo) bf16 split =================
__global__ __launch_bounds__(256) void split_f32_bf16(
    const float* __restrict__ src,
    __nv_bfloat16* __restrict__ hi, __nv_bfloat16* __restrict__ lo, int n)
{
    int i = (blockIdx.x * 256 + threadIdx.x) * 4;
    if (i >= n) return;
    float4 v = *(const float4*)(src + i);
    __nv_bfloat16 h0 = __float2bfloat16(v.x), h1 = __float2bfloat16(v.y);
    __nv_bfloat16 h2 = __float2bfloat16(v.z), h3 = __float2bfloat16(v.w);
    __nv_bfloat16 l0 = __float2bfloat16(v.x - __bfloat162float(h0));
    __nv_bfloat16 l1 = __float2bfloat16(v.y - __bfloat162float(h1));
    __nv_bfloat16 l2 = __float2bfloat16(v.z - __bfloat162float(h2));
    __nv_bfloat16 l3 = __float2bfloat16(v.w - __bfloat162float(h3));
    __nv_bfloat162* hp = (__nv_bfloat162*)(hi + i);
    __nv_bfloat162* lp = (__nv_bfloat162*)(lo + i);
    hp[0] = __nv_bfloat162(h0, h1); hp[1] = __nv_bfloat162(h2, h3);
    lp[0] = __nv_bfloat162(l0, l1); lp[1] = __nv_bfloat162(l2, l3);
}

// ================= HMMA + cp.async helpers (base ISA on sm_103) =================
__device__ __forceinline__ void mma16816(float* c, const uint32_t* a, const uint32_t* b)
{
    asm volatile(
        "mma.sync.aligned.m16n8k16.row.col.f32.bf16.bf16.f32 "
        "{%0,%1,%2,%3}, {%4,%5,%6,%7}, {%8,%9}, {%0,%1,%2,%3};"
        : "+f"(c[0]), "+f"(c[1]), "+f"(c[2]), "+f"(c[3])
        : "r"(a[0]), "r"(a[1]), "r"(a[2]), "r"(a[3]), "r"(b[0]), "r"(b[1]));
}
__device__ __forceinline__ uint32_t smem_u32(const void* p)
{
    uint32_t a;
    asm("{ .reg .u64 t; cvta.to.shared.u64 t, %1; cvt.u32.u64 %0, t; }"
        : "=r"(a) : "l"(p));
    return a;
}
__device__ __forceinline__ void cp_async16(uint32_t s, const void* g)
{
    asm volatile("cp.async.cg.shared.global [%0], [%1], 16;" :: "r"(s), "l"(g));
}
#define CP_COMMIT()  asm volatile("cp.async.commit_group;" ::: "memory")
#define CP_WAIT1()   asm volatile("cp.async.wait_group 1;" ::: "memory")
#define CP_WAIT0()   asm volatile("cp.async.wait_group 0;" ::: "memory")

// ================= HMMA 3-pass split-bf16 GEMM, cp.async double-buffered =====
// C[M,N] = Ah·Bh^T + Ah·Bl^T + Al·Bh^T + bias  (fp32 acc)
// Tile: 128 x BN, BK=32, 256 threads / 8 warps, 2-stage smem pipeline.
#define KP 40
template<int BN>
__global__ __launch_bounds__(256) void gemm_hmma_3p(
    const __nv_bfloat16* __restrict__ Ah, const __nv_bfloat16* __restrict__ Al,
    int lda, int aoff,
    const __nv_bfloat16* __restrict__ Bh, const __nv_bfloat16* __restrict__ Bl,
    const float* __restrict__ bias,
    float* __restrict__ C, int ldc, int Kdim)
{
    constexpr int GC = BN / 32;
    constexpr int GR = 8 / GC;
    constexpr int WM = 128 / GR;
    constexpr int MA = WM / 16;

    extern __shared__ __nv_bfloat16 smem[];
    // layout: A region [2 stages][2 parts][128][KP], then B [2][2][BN][KP]
    __nv_bfloat16* Abase = smem;
    __nv_bfloat16* Bbase = smem + 4 * 128 * KP;

    const int tid  = threadIdx.x;
    const int wid  = tid >> 5, lane = tid & 31;
    const int g    = lane >> 2, t = lane & 3;
    const int bm   = blockIdx.y * 128;
    const int bn   = blockIdx.x * BN;
    const int wm   = (wid / GC) * WM;
    const int wn   = (wid % GC) * 32;

    float acc[MA][4][4];
    #pragma unroll
    for (int im = 0; im < MA; im++)
        #pragma unroll
        for (int in_ = 0; in_ < 4; in_++)
            #pragma unroll
            for (int r = 0; r < 4; r++) acc[im][in_][r] = 0.f;

    // ---- async stage loader: chunk k0 = c*32 into stage s ----
    auto load_stage = [&](int s, int c) {
        const int k0 = c * 32;
        __nv_bfloat16* sAh = Abase + (s*2 + 0) * 128 * KP;
        __nv_bfloat16* sAl = Abase + (s*2 + 1) * 128 * KP;
        __nv_bfloat16* sBh = Bbase + (s*2 + 0) * BN * KP;
        __nv_bfloat16* sBl = Bbase + (s*2 + 1) * BN * KP;
        #pragma unroll
        for (int it = 0; it < 2; it++) {
            int idx = (tid + it * 256) * 8;
            int row = idx >> 5, col = idx & 31;
            long go = (long)(bm + row) * lda + aoff + k0 + col;
            cp_async16(smem_u32(sAh + row*KP + col), Ah + go);
            cp_async16(smem_u32(sAl + row*KP + col), Al + go);
        }
        #pragma unroll
        for (int it = 0; it < BN / 64; it++) {
            int idx = (tid + it * 256) * 8;
            int row = idx >> 5, col = idx & 31;
            long go = (long)(bn + row) * Kdim + k0 + col;
            cp_async16(smem_u32(sBh + row*KP + col), Bh + go);
            cp_async16(smem_u32(sBl + row*KP + col), Bl + go);
        }
    };

    const int nc = Kdim / 32;
    load_stage(0, 0);
    CP_COMMIT();

    for (int c = 0; c < nc; c++) {
        const int s = c & 1;
        if (c + 1 < nc) {
            load_stage(s ^ 1, c + 1);
            CP_COMMIT();
            CP_WAIT1();
        } else {
            CP_WAIT0();
        }
        __syncthreads();

        const __nv_bfloat16* sAh = Abase + (s*2 + 0) * 128 * KP;
        const __nv_bfloat16* sAl = Abase + (s*2 + 1) * 128 * KP;
        const __nv_bfloat16* sBh = Bbase + (s*2 + 0) * BN * KP;
        const __nv_bfloat16* sBl = Bbase + (s*2 + 1) * BN * KP;

        #pragma unroll
        for (int ks = 0; ks < 2; ks++) {
            const int kb = ks * 16;
            uint32_t ah[MA][4], al[MA][4];
            #pragma unroll
            for (int im = 0; im < MA; im++) {
                int r0 = wm + im * 16 + g;
                ah[im][0] = *(const uint32_t*)&sAh[(r0    )*KP + kb + t*2];
                ah[im][1] = *(const uint32_t*)&sAh[(r0 + 8)*KP + kb + t*2];
                ah[im][2] = *(const uint32_t*)&sAh[(r0    )*KP + kb + 8 + t*2];
                ah[im][3] = *(const uint32_t*)&sAh[(r0 + 8)*KP + kb + 8 + t*2];
                al[im][0] = *(const uint32_t*)&sAl[(r0    )*KP + kb + t*2];
                al[im][1] = *(const uint32_t*)&sAl[(r0 + 8)*KP + kb + t*2];
                al[im][2] = *(const uint32_t*)&sAl[(r0    )*KP + kb + 8 + t*2];
                al[im][3] = *(const uint32_t*)&sAl[(r0 + 8)*KP + kb + 8 + t*2];
            }
            uint32_t bh[4][2], bl[4][2];
            #pragma unroll
            for (int in_ = 0; in_ < 4; in_++) {
                int r = wn + in_ * 8 + g;
                bh[in_][0] = *(const uint32_t*)&sBh[r*KP + kb + t*2];
                bh[in_][1] = *(const uint32_t*)&sBh[r*KP + kb + 8 + t*2];
                bl[in_][0] = *(const uint32_t*)&sBl[r*KP + kb + t*2];
                bl[in_][1] = *(const uint32_t*)&sBl[r*KP + kb + 8 + t*2];
            }
            #pragma unroll
            for (int im = 0; im < MA; im++)
                #pragma unroll
                for (int in_ = 0; in_ < 4; in_++) {
                    mma16816(acc[im][in_], ah[im], bh[in_]);
                    mma16816(acc[im][in_], ah[im], bl[in_]);
                    mma16816(acc[im][in_], al[im], bh[in_]);
                }
        }
        __syncthreads();   // all warps done with stage s before it is refilled
    }

    #pragma unroll
    for (int im = 0; im < MA; im++) {
        #pragma unroll
        for (int in_ = 0; in_ < 4; in_++) {
            int col = bn + wn + in_ * 8 + t * 2;
            float2 bv = *(const float2*)(bias + col);
            int r0 = bm + wm + im * 16 + g;
            float2 v0 = { acc[im][in_][0] + bv.x, acc[im][in_][1] + bv.y };
            float2 v1 = { acc[im][in_][2] + bv.x, acc[im][in_][3] + bv.y };
            *(float2*)(C + (long)r0 * ldc + col)       = v0;
            *(float2*)(C + (long)(r0 + 8) * ldc + col) = v1;
        }
    }
}

#define GA128 ((4*128*KP + 4*128*KP) * 2)   // 81920 B
#define GA64  ((4*128*KP + 4*64*KP)  * 2)   // 61440 B

// ================= RoPE =================
__device__ __forceinline__ void rope_pair(int pos, int j, float& x1, float& x2)
{
    const float LOG2_THETA = 13.287712379549449f;
    float e   = (float)(2 * j) * (1.0f / (float)RD_);
    float inv = exp2f(-e * LOG2_THETA);
    float ang = (float)pos * inv;
    float s, c;
    sincosf(ang, &s, &c);
    float a = x1, b = x2;
    x1 = a * c - b * s;
    x2 = b * c + a * s;
}

__global__ void rope_kr_kernel()
{
    int r = blockIdx.x, j = threadIdx.x;
    int pos = r & (T_ - 1);
    float* p = g_KR + (long)r * RD_;
    float x1 = p[j], x2 = p[j + 32];
    rope_pair(pos, j, x1, x2);
    p[j] = x1; p[j + 32] = x2;
}

__global__ void rope_q_kernel()
{
    int r = blockIdx.x, tid = threadIdx.x;
    int h = tid >> 5, j = tid & 31;
    int pos = r & (T_ - 1);
    float* p = g_Q + (long)r * D_ + h * HD_ + CD_;
    float x1 = p[j], x2 = p[j + 32];
    rope_pair(pos, j, x1, x2);
    p[j] = x1; p[j + 32] = x2;
}

// ================= fp32 flash attention (FFMA2 core, known-good from R8) ======
#define FL_SMEM_FLOATS (2*128*68 + 64*128 + 64*65 + 3*64)
#define FL_SMEM_BYTES  (FL_SMEM_FLOATS * 4)

__global__ __launch_bounds__(256) void flash_kernel()
{
    extern __shared__ float sm[];
    float* sQt = sm;
    float* sKt = sQt + 128*68;
    float* sV  = sKt + 128*68;
    float* sP  = sV  + 64*128;
    float* sM  = sP  + 64*65;
    float* sL  = sM  + 64;
    float* sSc = sL  + 64;

    const int qt = 31 - blockIdx.x;
    const int pr = blockIdx.y;
    const int b  = pr >> 4, h = pr & 15;
    const int tid = threadIdx.x;
    const int tx = tid & 15, ty = tid >> 4;
    const int q0 = qt * 64;
    const int rowbase = b * T_;

    #pragma unroll 8
    for (int idx = tid; idx < 64*128; idx += 256) {
        int qi = idx >> 7, d = idx & 127;
        sQt[d*68 + qi] = g_Q[(long)(rowbase + q0 + qi) * D_ + h*HD_ + d];
    }
    if (tid < 64) { sM[tid] = -INFINITY; sL[tid] = 0.f; }

    ull accO2[4][4];
    #pragma unroll
    for (int i = 0; i < 4; i++)
        #pragma unroll
        for (int jp = 0; jp < 4; jp++) accO2[i][jp] = 0ull;

    const float sc_qk = 0.08838834764831845f;

    for (int kb = 0; kb <= qt; kb++) {
        const int k0 = kb * 64;
        __syncthreads();
        #pragma unroll 8
        for (int idx = tid; idx < 64*128; idx += 256) {
            int ki = idx >> 7, d = idx & 127;
            int r  = rowbase + k0 + ki;
            float kv = (d < CD_) ? g_KC[(long)r * (H_*CD_) + h*CD_ + d]
                                 : g_KR[(long)r * RD_ + (d - CD_)];
            sKt[d*68 + ki]  = kv;
            sV [ki*128 + d] = g_V[(long)r * D_ + h*HD_ + d];
        }
        __syncthreads();

        ull s2[4][2];
        #pragma unroll
        for (int i = 0; i < 4; i++) { s2[i][0] = 0ull; s2[i][1] = 0ull; }
        #pragma unroll 4
        for (int d = 0; d < 128; d++) {
            float4 a = *(const float4*)&sQt[d*68 + ty*4];
            ulonglong2 kp = *(const ulonglong2*)&sKt[d*68 + tx*4];
            ull a0 = splat2(a.x), a1 = splat2(a.y);
            ull a2 = splat2(a.z), a3 = splat2(a.w);
            s2[0][0] = ffma2(a0, kp.x, s2[0][0]); s2[0][1] = ffma2(a0, kp.y, s2[0][1]);
            s2[1][0] = ffma2(a1, kp.x, s2[1][0]); s2[1][1] = ffma2(a1, kp.y, s2[1][1]);
            s2[2][0] = ffma2(a2, kp.x, s2[2][0]); s2[2][1] = ffma2(a2, kp.y, s2[2][1]);
            s2[3][0] = ffma2(a3, kp.x, s2[3][0]); s2[3][1] = ffma2(a3, kp.y, s2[3][1]);
        }
        {
            const bool diag = (kb == qt);
            #pragma unroll
            for (int i = 0; i < 4; i++) {
                #pragma unroll
                for (int jp = 0; jp < 2; jp++) {
                    float2 sv = unpack2(s2[i][jp]);
                    int j0 = tx*4 + jp*2;
                    float v0 = sv.x * sc_qk;
                    float v1 = sv.y * sc_qk;
                    if (diag && (j0     > ty*4 + i)) v0 = -INFINITY;
                    if (diag && (j0 + 1 > ty*4 + i)) v1 = -INFINITY;
                    sP[(ty*4 + i)*65 + j0]     = v0;
                    sP[(ty*4 + i)*65 + j0 + 1] = v1;
                }
            }
        }
        __syncthreads();

        if (tid < 64) {
            float* row = sP + tid*65;
            float mold = sM[tid];
            float mx = mold;
            #pragma unroll 8
            for (int j = 0; j < 64; j++) mx = fmaxf(mx, row[j]);
            float scl = __expf(mold - mx);
            float sum = 0.f;
            #pragma unroll 8
            for (int j = 0; j < 64; j++) {
                float e = __expf(row[j] - mx);
                row[j] = e;
                sum += e;
            }
            sL[tid]  = sL[tid] * scl + sum;
            sM[tid]  = mx;
            sSc[tid] = scl;
        }
        __syncthreads();

        {
            ull f0 = splat2(sSc[ty*4+0]), f1 = splat2(sSc[ty*4+1]);
            ull f2 = splat2(sSc[ty*4+2]), f3 = splat2(sSc[ty*4+3]);
            #pragma unroll
            for (int jp = 0; jp < 4; jp++) {
                accO2[0][jp] = fmul2(accO2[0][jp], f0);
                accO2[1][jp] = fmul2(accO2[1][jp], f1);
                accO2[2][jp] = fmul2(accO2[2][jp], f2);
                accO2[3][jp] = fmul2(accO2[3][jp], f3);
            }
        }
        #pragma unroll 2
        for (int k = 0; k < 64; k++) {
            ull p0 = splat2(sP[(ty*4+0)*65 + k]);
            ull p1 = splat2(sP[(ty*4+1)*65 + k]);
            ull p2 = splat2(sP[(ty*4+2)*65 + k]);
            ull p3 = splat2(sP[(ty*4+3)*65 + k]);
            ulonglong2 v0 = *(const ulonglong2*)&sV[k*128 + tx*8];
            ulonglong2 v1 = *(const ulonglong2*)&sV[k*128 + tx*8 + 4];
            accO2[0][0] = ffma2(p0, v0.x, accO2[0][0]);
            accO2[0][1] = ffma2(p0, v0.y, accO2[0][1]);
            accO2[0][2] = ffma2(p0, v1.x, accO2[0][2]);
            accO2[0][3] = ffma2(p0, v1.y, accO2[0][3]);
            accO2[1][0] = ffma2(p1, v0.x, accO2[1][0]);
            accO2[1][1] = ffma2(p1, v0.y, accO2[1][1]);
            accO2[1][2] = ffma2(p1, v1.x, accO2[1][2]);
            accO2[1][3] = ffma2(p1, v1.y, accO2[1][3]);
            accO2[2][0] = ffma2(p2, v0.x, accO2[2][0]);
            accO2[2][1] = ffma2(p2, v0.y, accO2[2][1]);
            accO2[2][2] = ffma2(p2, v1.x, accO2[2][2]);
            accO2[2][3] = ffma2(p2, v1.y, accO2[2][3]);
            accO2[3][0] = ffma2(p3, v0.x, accO2[3][0]);
            accO2[3][1] = ffma2(p3, v0.y, accO2[3][1]);
            accO2[3][2] = ffma2(p3, v1.x, accO2[3][2]);
            accO2[3][3] = ffma2(p3, v1.y, accO2[3][3]);
        }
    }

    #pragma unroll
    for (int i = 0; i < 4; i++) {
        float inv = 1.f / sL[ty*4 + i];
        float* outp = g_O + (long)(rowbase + q0 + ty*4 + i) * D_ + h*HD_ + tx*8;
        #pragma unroll
        for (int jp = 0; jp < 4; jp++) {
            float2 c = unpack2(accO2[i][jp]);
            outp[jp*2]     = c.x * inv;
            outp[jp*2 + 1] = c.y * inv;
        }
    }
}

// ================= launcher =================
extern "C" void kernel_launch(void* const* d_in, const int* in_sizes, int n_in,
                              void* d_out, int out_size)
{
    const float* x   = (const float*)d_in[0];
    const float* Wq  = (const float*)d_in[1];
    const float* bq  = (const float*)d_in[2];
    const float* Wkv = (const float*)d_in[3];
    const float* bkv = (const float*)d_in[4];
    const float* Wkr = (const float*)d_in[5];
    const float* bkr = (const float*)d_in[6];
    const float* Wku = (const float*)d_in[7];
    const float* bku = (const float*)d_in[8];
    const float* Wvu = (const float*)d_in[9];
    const float* bvu = (const float*)d_in[10];
    const float* Wo  = (const float*)d_in[11];
    const float* bo  = (const float*)d_in[12];
    float* out = (float*)d_out;

    void *pQ, *pKV, *pKR, *pKC, *pV, *pO;
    cudaGetSymbolAddress(&pQ,  g_Q);
    cudaGetSymbolAddress(&pKV, g_KV);
    cudaGetSymbolAddress(&pKR, g_KR);
    cudaGetSymbolAddress(&pKC, g_KC);
    cudaGetSymbolAddress(&pV,  g_V);
    cudaGetSymbolAddress(&pO,  g_O);
    void *pxh, *pxl, *pWqh, *pWql, *pWkvh, *pWkvl, *pWkrh, *pWkrl;
    void *pWkuh, *pWkul, *pWvuh, *pWvul, *pWoh, *pWol, *pKVh, *pKVl, *pOh, *pOl;
    cudaGetSymbolAddress(&pxh,  g_xh);   cudaGetSymbolAddress(&pxl,  g_xl);
    cudaGetSymbolAddress(&pWqh, g_Wqh);  cudaGetSymbolAddress(&pWql, g_Wql);
    cudaGetSymbolAddress(&pWkvh,g_Wkvh); cudaGetSymbolAddress(&pWkvl,g_Wkvl);
    cudaGetSymbolAddress(&pWkrh,g_Wkrh); cudaGetSymbolAddress(&pWkrl,g_Wkrl);
    cudaGetSymbolAddress(&pWkuh,g_Wkuh); cudaGetSymbolAddress(&pWkul,g_Wkul);
    cudaGetSymbolAddress(&pWvuh,g_Wvuh); cudaGetSymbolAddress(&pWvul,g_Wvul);
    cudaGetSymbolAddress(&pWoh, g_Woh);  cudaGetSymbolAddress(&pWol, g_Wol);
    cudaGetSymbolAddress(&pKVh, g_KVh);  cudaGetSymbolAddress(&pKVl, g_KVl);
    cudaGetSymbolAddress(&pOh,  g_Oh);   cudaGetSymbolAddress(&pOl,  g_Ol);

    cudaFuncSetAttribute(gemm_hmma_3p<128>,
                         cudaFuncAttributeMaxDynamicSharedMemorySize, GA128);
    cudaFuncSetAttribute(gemm_hmma_3p<64>,
                         cudaFuncAttributeMaxDynamicSharedMemorySize, GA64);
    cudaFuncSetAttribute(flash_kernel,
                         cudaFuncAttributeMaxDynamicSharedMemorySize, FL_SMEM_BYTES);

    auto SPL = [](const float* s, void* h, void* l, int n) {
        split_f32_bf16<<<n/1024, 256>>>(s, (__nv_bfloat16*)h, (__nv_bfloat16*)l, n);
    };

    // input + weight splits
    SPL(x,   pxh,   pxl,   M_*D_);
    SPL(Wq,  pWqh,  pWql,  D_*D_);
    SPL(Wkv, pWkvh, pWkvl, 2*LAT_*D_);
    SPL(Wkr, pWkrh, pWkrl, RD_*D_);
    SPL(Wku, pWkuh, pWkul, H_*CD_*LAT_);
    SPL(Wvu, pWvuh, pWvul, D_*LAT_);
    SPL(Wo,  pWoh,  pWol,  D_*D_);

    // Q = x Wq^T + bq
    gemm_hmma_3p<128><<<dim3(16, 32), 256, GA128>>>(
        (__nv_bfloat16*)pxh, (__nv_bfloat16*)pxl, D_, 0,
        (__nv_bfloat16*)pWqh, (__nv_bfloat16*)pWql, bq, (float*)pQ, D_, D_);
    // KV = x Wkv^T + bkv
    gemm_hmma_3p<128><<<dim3(8, 32), 256, GA128>>>(
        (__nv_bfloat16*)pxh, (__nv_bfloat16*)pxl, D_, 0,
        (__nv_bfloat16*)pWkvh, (__nv_bfloat16*)pWkvl, bkv, (float*)pKV, 2*LAT_, D_);
    // KR = x Wkr^T + bkr
    gemm_hmma_3p<64><<<dim3(1, 32), 256, GA64>>>(
        (__nv_bfloat16*)pxh, (__nv_bfloat16*)pxl, D_, 0,
        (__nv_bfloat16*)pWkrh, (__nv_bfloat16*)pWkrl, bkr, (float*)pKR, RD_, D_);
    rope_kr_kernel<<<M_, 32>>>();

    // split KV for up-projections
    SPL((const float*)pKV, pKVh, pKVl, M_*2*LAT_);

    // KC = k_lat Wku^T + bku
    gemm_hmma_3p<128><<<dim3(8, 32), 256, GA128>>>(
        (__nv_bfloat16*)pKVh, (__nv_bfloat16*)pKVl, 2*LAT_, 0,
        (__nv_bfloat16*)pWkuh, (__nv_bfloat16*)pWkul, bku, (float*)pKC, H_*CD_, LAT_);
    // V = v_lat Wvu^T + bvu
    gemm_hmma_3p<128><<<dim3(16, 32), 256, GA128>>>(
        (__nv_bfloat16*)pKVh, (__nv_bfloat16*)pKVl, 2*LAT_, LAT_,
        (__nv_bfloat16*)pWvuh, (__nv_bfloat16*)pWvul, bvu, (float*)pV, D_, LAT_);

    rope_q_kernel<<<M_, 512>>>();
    flash_kernel<<<dim3(32, 32), 256, FL_SMEM_BYTES>>>();

    // split O, then out = O Wo^T + bo
    SPL((const float*)pO, pOh, pOl, M_*D_);
    gemm_hmma_3p<128><<<dim3(16, 32), 256, GA128>>>(
        (__nv_bfloat16*)pOh, (__nv_bfloat16*)pOl, D_, 0,
        (__nv_bfloat16*)pWoh, (__nv_bfloat16*)pWol, bo, out, D_, D_);
}

// round 14
// speedup vs baseline: 1.9490x; 1.6042x over previous
#include <cuda_runtime.h>
#include <cuda_bf16.h>
#include <math.h>
#include <stdint.h>

#define B_   2
#define T_   2048
#define D_   2048
#define H_   16
#define HD_  128
#define LAT_ 512
#define RD_  64
#define CD_  64
#define M_   (B_*T_)   // 4096 rows total

// ================= scratch =================
__device__ float g_Q [M_*D_];
__device__ float g_KV[M_*2*LAT_];
__device__ float g_KR[M_*RD_];
__device__ float g_KC[M_*H_*CD_];
__device__ float g_V [M_*D_];
__device__ float g_O [M_*D_];

__device__ __nv_bfloat16 g_xh [M_*D_],        g_xl [M_*D_];
__device__ __nv_bfloat16 g_Wqh [D_*D_],       g_Wql [D_*D_];
__device__ __nv_bfloat16 g_Wkvh[2*LAT_*D_],   g_Wkvl[2*LAT_*D_];
__device__ __nv_bfloat16 g_Wkrh[RD_*D_],      g_Wkrl[RD_*D_];
__device__ __nv_bfloat16 g_Wkuh[H_*CD_*LAT_], g_Wkul[H_*CD_*LAT_];
__device__ __nv_bfloat16 g_Wvuh[D_*LAT_],     g_Wvul[D_*LAT_];
__device__ __nv_bfloat16 g_Woh [D_*D_],       g_Wol [D_*D_];
__device__ __nv_bfloat16 g_KVh [M_*2*LAT_],   g_KVl [M_*2*LAT_];
__device__ __nv_bfloat16 g_Oh  [M_*D_],       g_Ol  [M_*D_];

// pre-split flash operands (bf16 hi/lo)
__device__ __nv_bfloat16 g_Qbh [M_*D_],       g_Qbl [M_*D_];
__device__ __nv_bfloat16 g_KCbh[M_*H_*CD_],   g_KCbl[M_*H_*CD_];
__device__ __nv_bfloat16 g_KRbh[M_*RD_],      g_KRbl[M_*RD_];
__device__ __nv_bfloat16 g_Vbh [M_*D_],       g_Vbl [M_*D_];

// ================= fp32 -> (hi, lo) bf16 split =================
__global__ __launch_bounds__(256) void split_f32_bf16(
    const float* __restrict__ src,
    __nv_bfloat16* __restrict__ hi, __nv_bfloat16* __restrict__ lo, int n)
{
    int i = (blockIdx.x * 256 + threadIdx.x) * 4;
    if (i >= n) return;
    float4 v = *(const float4*)(src + i);
    __nv_bfloat16 h0 = __float2bfloat16(v.x), h1 = __float2bfloat16(v.y);
    __nv_bfloat16 h2 = __float2bfloat16(v.z), h3 = __float2bfloat16(v.w);
    __nv_bfloat16 l0 = __float2bfloat16(v.x - __bfloat162float(h0));
    __nv_bfloat16 l1 = __float2bfloat16(v.y - __bfloat162float(h1));
    __nv_bfloat16 l2 = __float2bfloat16(v.z - __bfloat162float(h2));
    __nv_bfloat16 l3 = __float2bfloat16(v.w - __bfloat162float(h3));
    __nv_bfloat162* hp = (__nv_bfloat162*)(hi + i);
    __nv_bfloat162* lp = (__nv_bfloat162*)(lo + i);
    hp[0] = __nv_bfloat162(h0, h1); hp[1] = __nv_bfloat162(h2, h3);
    lp[0] = __nv_bfloat162(l0, l1); lp[1] = __nv_bfloat162(l2, l3);
}

// ================= HMMA + cp.async helpers (base ISA on sm_103) =================
__device__ __forceinline__ void mma16816(float* c, const uint32_t* a, const uint32_t* b)
{
    asm volatile(
        "mma.sync.aligned.m16n8k16.row.col.f32.bf16.bf16.f32 "
        "{%0,%1,%2,%3}, {%4,%5,%6,%7}, {%8,%9}, {%0,%1,%2,%3};"
        : "+f"(c[0]), "+f"(c[1]), "+f"(c[2]), "+f"(c[3])
        : "r"(a[0]), "r"(a[1]), "r"(a[2]), "r"(a[3]), "r"(b[0]), "r"(b[1]));
}
__device__ __forceinline__ void ldsm_x4_trans(uint32_t* r, uint32_t addr)
{
    asm volatile(
        "ldmatrix.sync.aligned.m8n8.x4.trans.shared.b16 {%0,%1,%2,%3}, [%4];"
        : "=r"(r[0]), "=r"(r[1]), "=r"(r[2]), "=r"(r[3]) : "r"(addr));
}
__device__ __forceinline__ uint32_t smem_u32(const void* p)
{
    uint32_t a;
    asm("{ .reg .u64 t; cvta.to.shared.u64 t, %1; cvt.u32.u64 %0, t; }"
        : "=r"(a) : "l"(p));
    return a;
}
__device__ __forceinline__ void cp_async16(uint32_t s, const void* g)
{
    asm volatile("cp.async.cg.shared.global [%0], [%1], 16;" :: "r"(s), "l"(g));
}
#define CP_COMMIT()  asm volatile("cp.async.commit_group;" ::: "memory")
#define CP_WAIT1()   asm volatile("cp.async.wait_group 1;" ::: "memory")
#define CP_WAIT0()   asm volatile("cp.async.wait_group 0;" ::: "memory")

// ================= HMMA 3-pass split-bf16 GEMM, cp.async double-buffered =====
#define KP 40
template<int BN>
__global__ __launch_bounds__(256) void gemm_hmma_3p(
    const __nv_bfloat16* __restrict__ Ah, const __nv_bfloat16* __restrict__ Al,
    int lda, int aoff,
    const __nv_bfloat16* __restrict__ Bh, const __nv_bfloat16* __restrict__ Bl,
    const float* __restrict__ bias,
    float* __restrict__ C, int ldc, int Kdim)
{
    constexpr int GC = BN / 32;
    constexpr int GR = 8 / GC;
    constexpr int WM = 128 / GR;
    constexpr int MA = WM / 16;

    extern __shared__ __nv_bfloat16 smem[];
    __nv_bfloat16* Abase = smem;
    __nv_bfloat16* Bbase = smem + 4 * 128 * KP;

    const int tid  = threadIdx.x;
    const int wid  = tid >> 5, lane = tid & 31;
    const int g    = lane >> 2, t = lane & 3;
    const int bm   = blockIdx.y * 128;
    const int bn   = blockIdx.x * BN;
    const int wm   = (wid / GC) * WM;
    const int wn   = (wid % GC) * 32;

    float acc[MA][4][4];
    #pragma unroll
    for (int im = 0; im < MA; im++)
        #pragma unroll
        for (int in_ = 0; in_ < 4; in_++)
            #pragma unroll
            for (int r = 0; r < 4; r++) acc[im][in_][r] = 0.f;

    auto load_stage = [&](int s, int c) {
        const int k0 = c * 32;
        __nv_bfloat16* sAh = Abase + (s*2 + 0) * 128 * KP;
        __nv_bfloat16* sAl = Abase + (s*2 + 1) * 128 * KP;
        __nv_bfloat16* sBh = Bbase + (s*2 + 0) * BN * KP;
        __nv_bfloat16* sBl = Bbase + (s*2 + 1) * BN * KP;
        #pragma unroll
        for (int it = 0; it < 2; it++) {
            int idx = (tid + it * 256) * 8;
            int row = idx >> 5, col = idx & 31;
            long go = (long)(bm + row) * lda + aoff + k0 + col;
            cp_async16(smem_u32(sAh + row*KP + col), Ah + go);
            cp_async16(smem_u32(sAl + row*KP + col), Al + go);
        }
        #pragma unroll
        for (int it = 0; it < BN / 64; it++) {
            int idx = (tid + it * 256) * 8;
            int row = idx >> 5, col = idx & 31;
            long go = (long)(bn + row) * Kdim + k0 + col;
            cp_async16(smem_u32(sBh + row*KP + col), Bh + go);
            cp_async16(smem_u32(sBl + row*KP + col), Bl + go);
        }
    };

    const int nc = Kdim / 32;
    load_stage(0, 0);
    CP_COMMIT();

    for (int c = 0; c < nc; c++) {
        const int s = c & 1;
        if (c + 1 < nc) {
            load_stage(s ^ 1, c + 1);
            CP_COMMIT();
            CP_WAIT1();
        } else {
            CP_WAIT0();
        }
        __syncthreads();

        const __nv_bfloat16* sAh = Abase + (s*2 + 0) * 128 * KP;
        const __nv_bfloat16* sAl = Abase + (s*2 + 1) * 128 * KP;
        const __nv_bfloat16* sBh = Bbase + (s*2 + 0) * BN * KP;
        const __nv_bfloat16* sBl = Bbase + (s*2 + 1) * BN * KP;

        #pragma unroll
        for (int ks = 0; ks < 2; ks++) {
            const int kb = ks * 16;
            uint32_t ah[MA][4], al[MA][4];
            #pragma unroll
            for (int im = 0; im < MA; im++) {
                int r0 = wm + im * 16 + g;
                ah[im][0] = *(const uint32_t*)&sAh[(r0    )*KP + kb + t*2];
                ah[im][1] = *(const uint32_t*)&sAh[(r0 + 8)*KP + kb + t*2];
                ah[im][2] = *(const uint32_t*)&sAh[(r0    )*KP + kb + 8 + t*2];
                ah[im][3] = *(const uint32_t*)&sAh[(r0 + 8)*KP + kb + 8 + t*2];
                al[im][0] = *(const uint32_t*)&sAl[(r0    )*KP + kb + t*2];
                al[im][1] = *(const uint32_t*)&sAl[(r0 + 8)*KP + kb + t*2];
                al[im][2] = *(const uint32_t*)&sAl[(r0    )*KP + kb + 8 + t*2];
                al[im][3] = *(const uint32_t*)&sAl[(r0 + 8)*KP + kb + 8 + t*2];
            }
            uint32_t bh[4][2], bl[4][2];
            #pragma unroll
            for (int in_ = 0; in_ < 4; in_++) {
                int r = wn + in_ * 8 + g;
                bh[in_][0] = *(const uint32_t*)&sBh[r*KP + kb + t*2];
                bh[in_][1] = *(const uint32_t*)&sBh[r*KP + kb + 8 + t*2];
                bl[in_][0] = *(const uint32_t*)&sBl[r*KP + kb + t*2];
                bl[in_][1] = *(const uint32_t*)&sBl[r*KP + kb + 8 + t*2];
            }
            #pragma unroll
            for (int im = 0; im < MA; im++)
                #pragma unroll
                for (int in_ = 0; in_ < 4; in_++) {
                    mma16816(acc[im][in_], ah[im], bh[in_]);
                    mma16816(acc[im][in_], ah[im], bl[in_]);
                    mma16816(acc[im][in_], al[im], bh[in_]);
                }
        }
        __syncthreads();
    }

    #pragma unroll
    for (int im = 0; im < MA; im++) {
        #pragma unroll
        for (int in_ = 0; in_ < 4; in_++) {
            int col = bn + wn + in_ * 8 + t * 2;
            float2 bv = *(const float2*)(bias + col);
            int r0 = bm + wm + im * 16 + g;
            float2 v0 = { acc[im][in_][0] + bv.x, acc[im][in_][1] + bv.y };
            float2 v1 = { acc[im][in_][2] + bv.x, acc[im][in_][3] + bv.y };
            *(float2*)(C + (long)r0 * ldc + col)       = v0;
            *(float2*)(C + (long)(r0 + 8) * ldc + col) = v1;
        }
    }
}

#define GA128 ((4*128*KP + 4*128*KP) * 2)   // 81920 B
#define GA64  ((4*128*KP + 4*64*KP)  * 2)   // 61440 B

// ================= RoPE =================
__device__ __forceinline__ void rope_pair(int pos, int j, float& x1, float& x2)
{
    const float LOG2_THETA = 13.287712379549449f;
    float e   = (float)(2 * j) * (1.0f / (float)RD_);
    float inv = exp2f(-e * LOG2_THETA);
    float ang = (float)pos * inv;
    float s, c;
    sincosf(ang, &s, &c);
    float a = x1, b = x2;
    x1 = a * c - b * s;
    x2 = b * c + a * s;
}

__global__ void rope_kr_kernel()
{
    int r = blockIdx.x, j = threadIdx.x;
    int pos = r & (T_ - 1);
    float* p = g_KR + (long)r * RD_;
    float x1 = p[j], x2 = p[j + 32];
    rope_pair(pos, j, x1, x2);
    p[j] = x1; p[j + 32] = x2;
}

__global__ void rope_q_kernel()
{
    int r = blockIdx.x, tid = threadIdx.x;
    int h = tid >> 5, j = tid & 31;
    int pos = r & (T_ - 1);
    float* p = g_Q + (long)r * D_ + h * HD_ + CD_;
    float x1 = p[j], x2 = p[j + 32];
    rope_pair(pos, j, x1, x2);
    p[j] = x1; p[j + 32] = x2;
}

// ================= HMMA flash attention v2 ==============================
// Pre-split bf16 inputs; parallel softmax fused with P hi/lo conversion.
#define KP2 136
#define PP  72
#define FL2_SMEM (6*64*KP2*2 + 64*65*4 + 2*64*PP*2 + 3*64*4)   // 140288 B

__global__ __launch_bounds__(256) void flash_hmma2()
{
    extern __shared__ char smx[];
    __nv_bfloat16* sQh = (__nv_bfloat16*)smx;
    __nv_bfloat16* sQl = sQh + 64*KP2;
    __nv_bfloat16* sKh = sQl + 64*KP2;
    __nv_bfloat16* sKl = sKh + 64*KP2;
    __nv_bfloat16* sVh = sKl + 64*KP2;
    __nv_bfloat16* sVl = sVh + 64*KP2;
    float*         sP  = (float*)(sVl + 64*KP2);     // [64][65]
    __nv_bfloat16* sPh = (__nv_bfloat16*)(sP + 64*65);
    __nv_bfloat16* sPl = sPh + 64*PP;
    float*         sM  = (float*)(sPl + 64*PP);
    float*         sL  = sM + 64;
    float*         sSc = sL + 64;

    const int qt = 31 - blockIdx.x;
    const int pr = blockIdx.y;
    const int b  = pr >> 4, h = pr & 15;
    const int tid  = threadIdx.x;
    const int wid  = tid >> 5, lane = tid & 31;
    const int g    = lane >> 2, t = lane & 3;
    const int q0 = qt * 64;
    const int rowbase = b * T_;
    const int wm  = (wid >> 1) * 16;
    const int wnS = (wid & 1) * 32;
    const int wnO = (wid & 1) * 64;

    const uint32_t vhb = smem_u32(sVh);
    const uint32_t vlb = smem_u32(sVl);

    // ---- Q tile: direct bf16 copies ----
    for (int ci = tid; ci < 64*16; ci += 256) {
        int row = ci >> 4, dc = ci & 15;
        long gq = (long)(rowbase + q0 + row) * D_ + h*HD_ + dc*8;
        *(uint4*)&sQh[row*KP2 + dc*8] = *(const uint4*)(g_Qbh + gq);
        *(uint4*)&sQl[row*KP2 + dc*8] = *(const uint4*)(g_Qbl + gq);
    }
    if (tid < 64) { sM[tid] = -INFINITY; sL[tid] = 0.f; }

    float accO[8][4];
    #pragma unroll
    for (int a = 0; a < 8; a++)
        #pragma unroll
        for (int r = 0; r < 4; r++) accO[a][r] = 0.f;

    const float sc_qk = 0.08838834764831845f;

    for (int kb = 0; kb <= qt; kb++) {
        const int k0 = kb * 64;
        __syncthreads();   // S1
        // ---- K/V tiles: direct bf16 copies ----
        for (int ci = tid; ci < 64*16; ci += 256) {
            int row = ci >> 4, dc = ci & 15;
            long r = rowbase + k0 + row;
            uint4 kh4, kl4;
            if (dc < 8) {
                long gk = r * (long)(H_*CD_) + h*CD_ + dc*8;
                kh4 = *(const uint4*)(g_KCbh + gk);
                kl4 = *(const uint4*)(g_KCbl + gk);
            } else {
                long gk = r * (long)RD_ + (dc - 8)*8;
                kh4 = *(const uint4*)(g_KRbh + gk);
                kl4 = *(const uint4*)(g_KRbl + gk);
            }
            *(uint4*)&sKh[row*KP2 + dc*8] = kh4;
            *(uint4*)&sKl[row*KP2 + dc*8] = kl4;
            long gv = r * (long)D_ + h*HD_ + dc*8;
            *(uint4*)&sVh[row*KP2 + dc*8] = *(const uint4*)(g_Vbh + gv);
            *(uint4*)&sVl[row*KP2 + dc*8] = *(const uint4*)(g_Vbl + gv);
        }
        __syncthreads();   // S2

        // ---- QK^T: 3-pass (verified R10 mapping) ----
        float accS[4][4];
        #pragma unroll
        for (int in_ = 0; in_ < 4; in_++)
            #pragma unroll
            for (int r = 0; r < 4; r++) accS[in_][r] = 0.f;

        #pragma unroll
        for (int ks = 0; ks < 8; ks++) {
            const int kk = ks * 16;
            uint32_t ah[4], al[4];
            ah[0] = *(const uint32_t*)&sQh[(wm+g  )*KP2 + kk     + t*2];
            ah[1] = *(const uint32_t*)&sQh[(wm+g+8)*KP2 + kk     + t*2];
            ah[2] = *(const uint32_t*)&sQh[(wm+g  )*KP2 + kk + 8 + t*2];
            ah[3] = *(const uint32_t*)&sQh[(wm+g+8)*KP2 + kk + 8 + t*2];
            al[0] = *(const uint32_t*)&sQl[(wm+g  )*KP2 + kk     + t*2];
            al[1] = *(const uint32_t*)&sQl[(wm+g+8)*KP2 + kk     + t*2];
            al[2] = *(const uint32_t*)&sQl[(wm+g  )*KP2 + kk + 8 + t*2];
            al[3] = *(const uint32_t*)&sQl[(wm+g+8)*KP2 + kk + 8 + t*2];
            #pragma unroll
            for (int in_ = 0; in_ < 4; in_++) {
                int r = wnS + in_*8 + g;
                uint32_t bh[2], bl[2];
                bh[0] = *(const uint32_t*)&sKh[r*KP2 + kk     + t*2];
                bh[1] = *(const uint32_t*)&sKh[r*KP2 + kk + 8 + t*2];
                bl[0] = *(const uint32_t*)&sKl[r*KP2 + kk     + t*2];
                bl[1] = *(const uint32_t*)&sKl[r*KP2 + kk + 8 + t*2];
                mma16816(accS[in_], ah, bh);
                mma16816(accS[in_], ah, bl);
                mma16816(accS[in_], al, bh);
            }
        }

        // ---- write masked, scaled S ----
        {
            const bool diag = (kb == qt);
            #pragma unroll
            for (int in_ = 0; in_ < 4; in_++) {
                int c0 = wnS + in_*8 + t*2;
                int r0 = wm + g, r1 = wm + g + 8;
                float v0 = accS[in_][0] * sc_qk;
                float v1 = accS[in_][1] * sc_qk;
                float v2 = accS[in_][2] * sc_qk;
                float v3 = accS[in_][3] * sc_qk;
                if (diag) {
                    if (c0     > r0) v0 = -INFINITY;
                    if (c0 + 1 > r0) v1 = -INFINITY;
                    if (c0     > r1) v2 = -INFINITY;
                    if (c0 + 1 > r1) v3 = -INFINITY;
                }
                sP[r0*65 + c0] = v0; sP[r0*65 + c0 + 1] = v1;
                sP[r1*65 + c0] = v2; sP[r1*65 + c0 + 1] = v3;
            }
        }
        __syncthreads();   // S3

        // ---- parallel softmax + P hi/lo (4 threads per row, all warps) ----
        {
            int r = tid >> 2, c = tid & 3;
            const float* row = sP + r*65 + c*16;
            float v[16];
            float mx = -INFINITY;
            #pragma unroll
            for (int j = 0; j < 16; j++) { v[j] = row[j]; mx = fmaxf(mx, v[j]); }
            mx = fmaxf(mx, __shfl_xor_sync(0xffffffffu, mx, 1));
            mx = fmaxf(mx, __shfl_xor_sync(0xffffffffu, mx, 2));
            float mold = sM[r];
            float mnew = fmaxf(mold, mx);
            float sum = 0.f;
            __nv_bfloat16* ph = sPh + r*PP + c*16;
            __nv_bfloat16* pl = sPl + r*PP + c*16;
            #pragma unroll
            for (int j = 0; j < 16; j++) {
                float e = __expf(v[j] - mnew);
                __nv_bfloat16 eh = __float2bfloat16(e);
                ph[j] = eh;
                pl[j] = __float2bfloat16(e - __bfloat162float(eh));
                sum += e;
            }
            sum += __shfl_xor_sync(0xffffffffu, sum, 1);
            sum += __shfl_xor_sync(0xffffffffu, sum, 2);
            if (c == 0) {
                float scl = __expf(mold - mnew);
                sL[r]  = sL[r] * scl + sum;
                sM[r]  = mnew;
                sSc[r] = scl;
            }
        }
        __syncthreads();   // S4

        // ---- rescale accO, then O += P V (3-pass, verified R10 mapping) ----
        {
            float f0 = sSc[wm + g], f1 = sSc[wm + g + 8];
            #pragma unroll
            for (int a = 0; a < 8; a++) {
                accO[a][0] *= f0; accO[a][1] *= f0;
                accO[a][2] *= f1; accO[a][3] *= f1;
            }
        }
        #pragma unroll
        for (int ks = 0; ks < 4; ks++) {
            const int kk = ks * 16;
            uint32_t ah[4], al[4];
            ah[0] = *(const uint32_t*)&sPh[(wm+g  )*PP + kk     + t*2];
            ah[1] = *(const uint32_t*)&sPh[(wm+g+8)*PP + kk     + t*2];
            ah[2] = *(const uint32_t*)&sPh[(wm+g  )*PP + kk + 8 + t*2];
            ah[3] = *(const uint32_t*)&sPh[(wm+g+8)*PP + kk + 8 + t*2];
            al[0] = *(const uint32_t*)&sPl[(wm+g  )*PP + kk     + t*2];
            al[1] = *(const uint32_t*)&sPl[(wm+g+8)*PP + kk     + t*2];
            al[2] = *(const uint32_t*)&sPl[(wm+g  )*PP + kk + 8 + t*2];
            al[3] = *(const uint32_t*)&sPl[(wm+g+8)*PP + kk + 8 + t*2];
            #pragma unroll
            for (int pair = 0; pair < 4; pair++) {
                int n0 = wnO + pair * 16;
                int klocal = kk + (lane & 15);
                int dloc   = n0 + ((lane >> 4) << 3);
                uint32_t off = (uint32_t)(klocal * KP2 + dloc) * 2;
                uint32_t bh4[4], bl4[4];
                ldsm_x4_trans(bh4, vhb + off);
                ldsm_x4_trans(bl4, vlb + off);
                mma16816(accO[pair*2    ], ah, bh4);
                mma16816(accO[pair*2    ], ah, bl4);
                mma16816(accO[pair*2    ], al, bh4);
                mma16816(accO[pair*2 + 1], ah, bh4 + 2);
                mma16816(accO[pair*2 + 1], ah, bl4 + 2);
                mma16816(accO[pair*2 + 1], al, bh4 + 2);
            }
        }
    }

    // ---- final: divide by L, store O ----
    {
        float inv0 = 1.f / sL[wm + g];
        float inv1 = 1.f / sL[wm + g + 8];
        long r0 = (long)(rowbase + q0 + wm + g) * D_;
        long r1 = (long)(rowbase + q0 + wm + g + 8) * D_;
        #pragma unroll
        for (int a = 0; a < 8; a++) {
            int col = h*HD_ + wnO + (a >> 1) * 16 + (a & 1) * 8 + t*2;
            float2 v0 = { accO[a][0] * inv0, accO[a][1] * inv0 };
            float2 v1 = { accO[a][2] * inv1, accO[a][3] * inv1 };
            *(float2*)(g_O + r0 + col) = v0;
            *(float2*)(g_O + r1 + col) = v1;
        }
    }
}

// ================= launcher =================
extern "C" void kernel_launch(void* const* d_in, const int* in_sizes, int n_in,
                              void* d_out, int out_size)
{
    const float* x   = (const float*)d_in[0];
    const float* Wq  = (const float*)d_in[1];
    const float* bq  = (const float*)d_in[2];
    const float* Wkv = (const float*)d_in[3];
    const float* bkv = (const float*)d_in[4];
    const float* Wkr = (const float*)d_in[5];
    const float* bkr = (const float*)d_in[6];
    const float* Wku = (const float*)d_in[7];
    const float* bku = (const float*)d_in[8];
    const float* Wvu = (const float*)d_in[9];
    const float* bvu = (const float*)d_in[10];
    const float* Wo  = (const float*)d_in[11];
    const float* bo  = (const float*)d_in[12];
    float* out = (float*)d_out;

    void *pQ, *pKV, *pKR, *pKC, *pV, *pO;
    cudaGetSymbolAddress(&pQ,  g_Q);
    cudaGetSymbolAddress(&pKV, g_KV);
    cudaGetSymbolAddress(&pKR, g_KR);
    cudaGetSymbolAddress(&pKC, g_KC);
    cudaGetSymbolAddress(&pV,  g_V);
    cudaGetSymbolAddress(&pO,  g_O);
    void *pxh, *pxl, *pWqh, *pWql, *pWkvh, *pWkvl, *pWkrh, *pWkrl;
    void *pWkuh, *pWkul, *pWvuh, *pWvul, *pWoh, *pWol, *pKVh, *pKVl, *pOh, *pOl;
    void *pQbh, *pQbl, *pKCbh, *pKCbl, *pKRbh, *pKRbl, *pVbh, *pVbl;
    cudaGetSymbolAddress(&pxh,  g_xh);   cudaGetSymbolAddress(&pxl,  g_xl);
    cudaGetSymbolAddress(&pWqh, g_Wqh);  cudaGetSymbolAddress(&pWql, g_Wql);
    cudaGetSymbolAddress(&pWkvh,g_Wkvh); cudaGetSymbolAddress(&pWkvl,g_Wkvl);
    cudaGetSymbolAddress(&pWkrh,g_Wkrh); cudaGetSymbolAddress(&pWkrl,g_Wkrl);
    cudaGetSymbolAddress(&pWkuh,g_Wkuh); cudaGetSymbolAddress(&pWkul,g_Wkul);
    cudaGetSymbolAddress(&pWvuh,g_Wvuh); cudaGetSymbolAddress(&pWvul,g_Wvul);
    cudaGetSymbolAddress(&pWoh, g_Woh);  cudaGetSymbolAddress(&pWol, g_Wol);
    cudaGetSymbolAddress(&pKVh, g_KVh);  cudaGetSymbolAddress(&pKVl, g_KVl);
    cudaGetSymbolAddress(&pOh,  g_Oh);   cudaGetSymbolAddress(&pOl,  g_Ol);
    cudaGetSymbolAddress(&pQbh, g_Qbh);  cudaGetSymbolAddress(&pQbl, g_Qbl);
    cudaGetSymbolAddress(&pKCbh,g_KCbh); cudaGetSymbolAddress(&pKCbl,g_KCbl);
    cudaGetSymbolAddress(&pKRbh,g_KRbh); cudaGetSymbolAddress(&pKRbl,g_KRbl);
    cudaGetSymbolAddress(&pVbh, g_Vbh);  cudaGetSymbolAddress(&pVbl, g_Vbl);

    cudaFuncSetAttribute(gemm_hmma_3p<128>,
                         cudaFuncAttributeMaxDynamicSharedMemorySize, GA128);
    cudaFuncSetAttribute(gemm_hmma_3p<64>,
                         cudaFuncAttributeMaxDynamicSharedMemorySize, GA64);
    cudaFuncSetAttribute(flash_hmma2,
                         cudaFuncAttributeMaxDynamicSharedMemorySize, FL2_SMEM);

    auto SPL = [](const float* s, void* h, void* l, int n) {
        split_f32_bf16<<<n/1024, 256>>>(s, (__nv_bfloat16*)h, (__nv_bfloat16*)l, n);
    };

    // input + weight splits
    SPL(x,   pxh,   pxl,   M_*D_);
    SPL(Wq,  pWqh,  pWql,  D_*D_);
    SPL(Wkv, pWkvh, pWkvl, 2*LAT_*D_);
    SPL(Wkr, pWkrh, pWkrl, RD_*D_);
    SPL(Wku, pWkuh, pWkul, H_*CD_*LAT_);
    SPL(Wvu, pWvuh, pWvul, D_*LAT_);
    SPL(Wo,  pWoh,  pWol,  D_*D_);

    // Q = x Wq^T + bq
    gemm_hmma_3p<128><<<dim3(16, 32), 256, GA128>>>(
        (__nv_bfloat16*)pxh, (__nv_bfloat16*)pxl, D_, 0,
        (__nv_bfloat16*)pWqh, (__nv_bfloat16*)pWql, bq, (float*)pQ, D_, D_);
    // KV = x Wkv^T + bkv
    gemm_hmma_3p<128><<<dim3(8, 32), 256, GA128>>>(
        (__nv_bfloat16*)pxh, (__nv_bfloat16*)pxl, D_, 0,
        (__nv_bfloat16*)pWkvh, (__nv_bfloat16*)pWkvl, bkv, (float*)pKV, 2*LAT_, D_);
    // KR = x Wkr^T + bkr
    gemm_hmma_3p<64><<<dim3(1, 32), 256, GA64>>>(
        (__nv_bfloat16*)pxh, (__nv_bfloat16*)pxl, D_, 0,
        (__nv_bfloat16*)pWkrh, (__nv_bfloat16*)pWkrl, bkr, (float*)pKR, RD_, D_);
    rope_kr_kernel<<<M_, 32>>>();

    // split KV for up-projections
    SPL((const float*)pKV, pKVh, pKVl, M_*2*LAT_);

    // KC = k_lat Wku^T + bku
    gemm_hmma_3p<128><<<dim3(8, 32), 256, GA128>>>(
        (__nv_bfloat16*)pKVh, (__nv_bfloat16*)pKVl, 2*LAT_, 0,
        (__nv_bfloat16*)pWkuh, (__nv_bfloat16*)pWkul, bku, (float*)pKC, H_*CD_, LAT_);
    // V = v_lat Wvu^T + bvu
    gemm_hmma_3p<128><<<dim3(16, 32), 256, GA128>>>(
        (__nv_bfloat16*)pKVh, (__nv_bfloat16*)pKVl, 2*LAT_, LAT_,
        (__nv_bfloat16*)pWvuh, (__nv_bfloat16*)pWvul, bvu, (float*)pV, D_, LAT_);

    rope_q_kernel<<<M_, 512>>>();

    // pre-split flash operands to bf16 hi/lo
    SPL((const float*)pQ,  pQbh,  pQbl,  M_*D_);
    SPL((const float*)pKC, pKCbh, pKCbl, M_*H_*CD_);
    SPL((const float*)pKR, pKRbh, pKRbl, M_*RD_);
    SPL((const float*)pV,  pVbh,  pVbl,  M_*D_);

    flash_hmma2<<<dim3(32, 32), 256, FL2_SMEM>>>();

    // split O, then out = O Wo^T + bo
    SPL((const float*)pO, pOh, pOl, M_*D_);
    gemm_hmma_3p<128><<<dim3(16, 32), 256, GA128>>>(
        (__nv_bfloat16*)pOh, (__nv_bfloat16*)pOl, D_, 0,
        (__nv_bfloat16*)pWoh, (__nv_bfloat16*)pWol, bo, out, D_, D_);
}